// round 4
// baseline (speedup 1.0000x reference)
#include <cuda_runtime.h>
#include <math.h>

#define BB 4
#define NN 128
#define FF 128
#define SS 5
#define TGLOB 32
#define LL 2
#define TBL 512
#define LMAX 16.0f
#define TBL_SCALE (TBL / LMAX)

// ---------------- persistent scratch (device globals; no allocation) ------
__device__ float g_posbuf[2][BB * NN * 3];
__device__ float g_vecbuf[2][BB * NN * 3 * FF];   // [p][b][n][d][c]
__device__ float g_zbuf[2][BB * NN * FF];
__device__ float g_tbl[LL * TBL * 512];           // radial table [layer][t][c*4+j]

// ---------------- table build: 8 rows per block for Wr2 reuse -------------
__global__ __launch_bounds__(128) void k_tables(const float* __restrict__ Wr1,
                                                const float* __restrict__ br1,
                                                const float* __restrict__ Wr2) {
    const int tb0 = blockIdx.x * 8;     // first of 8 table rows
    const int i = blockIdx.y;           // layer
    const int c = threadIdx.x;
    __shared__ float h[8][64];
    if (c < 64) {
        float w1 = Wr1[i * 64 + c];
        float b1 = br1[i * 64 + c];
#pragma unroll
        for (int j = 0; j < 8; j++) {
            float lng = (float)(tb0 + j) * (LMAX / (float)TBL);
            float p = lng * w1 + b1;
            h[j][c] = p / (1.0f + expf(-p));
        }
    }
    __syncthreads();
    const float* W = Wr2 + i * 64 * 512 + c;
    float acc[8][4];
#pragma unroll
    for (int j = 0; j < 8; j++)
#pragma unroll
        for (int d = 0; d < 4; d++) acc[j][d] = 0.f;
#pragma unroll 4
    for (int m = 0; m < 64; m++) {
        float w0 = W[m * 512 + 0];
        float w1v = W[m * 512 + 128];
        float w2 = W[m * 512 + 256];
        float w3 = W[m * 512 + 384];
#pragma unroll
        for (int j = 0; j < 8; j++) {
            float hm = h[j][m];
            acc[j][0] = fmaf(hm, w0, acc[j][0]);
            acc[j][1] = fmaf(hm, w1v, acc[j][1]);
            acc[j][2] = fmaf(hm, w2, acc[j][2]);
            acc[j][3] = fmaf(hm, w3, acc[j][3]);
        }
    }
#pragma unroll
    for (int j = 0; j < 8; j++) {
        float* dst = g_tbl + ((size_t)i * TBL + tb0 + j) * 512 + c * 4;
        dst[0] = acc[j][0]; dst[1] = acc[j][1]; dst[2] = acc[j][2]; dst[3] = acc[j][3];
    }
}

// ---------------- init: embed scalars, zero vectors, z(layer0), pos -------
__global__ __launch_bounds__(128) void k_init(const float* __restrict__ positions,
                                              const int* __restrict__ node_features,
                                              const float* __restrict__ gf,
                                              const float* __restrict__ W_embed,
                                              const float* __restrict__ b_embed,
                                              const float* __restrict__ Wnode) {
    int bn = blockIdx.x;
    int b = bn / NN;
    int c = threadIdx.x;
    int nf = node_features[bn];
    float s = W_embed[(nf - 1) * FF + c] + b_embed[c];
#pragma unroll 8
    for (int t = 0; t < TGLOB; t++)
        s = fmaf(gf[b * TGLOB + t], W_embed[(SS + t) * FF + c], s);
    g_vecbuf[0][bn * 3 * FF + 0 * FF + c] = 0.f;
    g_vecbuf[0][bn * 3 * FF + 1 * FF + c] = 0.f;
    g_vecbuf[0][bn * 3 * FF + 2 * FF + c] = 0.f;
    if (c < 3) g_posbuf[0][bn * 3 + c] = positions[bn * 3 + c];

    __shared__ float srow[FF];
    srow[c] = s;
    __syncthreads();
    float acc = 0.f;
#pragma unroll 8
    for (int k = 0; k < FF; k++)
        acc = fmaf(srow[k], Wnode[k * FF + c], acc);
    g_zbuf[0][bn * FF + c] = acc;
}

// ---------------- fused layer: message gather + gate + node update --------
// blockDim = (128, 4). Reads parity p, writes parity 1-p.
__global__ __launch_bounds__(512) void k_layer(const float* __restrict__ pos_in,
                                               const float* __restrict__ c1w,
                                               const float* __restrict__ c2w,
                                               const float* __restrict__ c3w,
                                               const float* __restrict__ Wmix0,
                                               const float* __restrict__ Wmix1,
                                               const float* __restrict__ Wg1,
                                               const float* __restrict__ Wg2,
                                               const float* __restrict__ Wvout,
                                               const float* __restrict__ Wnode,
                                               float* __restrict__ out,
                                               int layer) {
    const int r = blockIdx.x;
    const int b = blockIdx.y;
    const int c = threadIdx.x;
    const int q = threadIdx.y;
    const int tid = q * 128 + c;
    const int p = layer & 1;
    const int bn = b * NN + r;

    __shared__ float sp[NN * 3];
    __shared__ float sp0[NN * 3];
    __shared__ float red[3][16 * FF];      // reused as part[] later
    __shared__ float sA[4 * FF];
    __shared__ float sscal[FF];
    __shared__ float shp[4][16];
    __shared__ float sh[16];
    __shared__ float rb[3][4];

    const float* posp = g_posbuf[p] + b * NN * 3;
    for (int idx = tid; idx < NN * 3; idx += 512) {
        sp[idx]  = posp[idx];
        sp0[idx] = pos_in[b * NN * 3 + idx];
    }
    __syncthreads();

    const float rx = sp[r * 3 + 0], ry = sp[r * 3 + 1], rz = sp[r * 3 + 2];
    const float r0x = sp0[r * 3 + 0], r0y = sp0[r * 3 + 1], r0z = sp0[r * 3 + 2];

    const float s3 = 1.7320508075688772f, s5 = 2.2360679774997896f,
                s15 = 3.872983346207417f, s35_8 = 2.091650066335189f,
                s105 = 10.246950765959598f, s21_8 = 1.6201851746019651f,
                s7 = 2.6457513110645907f;

    float A[16];
#pragma unroll
    for (int k = 0; k < 16; k++) A[k] = 0.f;

    const float* tb = g_tbl + (size_t)layer * TBL * 512;
    const float* zbase = g_zbuf[p] + b * NN * FF;
    const float* vbase = g_vecbuf[p] + b * NN * 3 * FF;

    for (int s = q; s < NN; s += 4) {
        if (s == r) continue;
        float dx0 = r0x - sp0[s * 3 + 0];
        float dy0 = r0y - sp0[s * 3 + 1];
        float dz0 = r0z - sp0[s * 3 + 2];
        float l0 = sqrtf(dx0 * dx0 + dy0 * dy0 + dz0 * dz0 + 1e-12f);
        float env = (l0 < 10.0f) ? 0.5f * (cosf(l0 * 0.3141592653589793f) + 1.0f) : 0.0f;
        if (env == 0.0f) continue;

        float vx = rx - sp[s * 3 + 0];
        float vy = ry - sp[s * 3 + 1];
        float vz = rz - sp[s * 3 + 2];
        float lng = sqrtf(vx * vx + vy * vy + vz * vz + 1e-12f);
        float inv = 1.0f / lng;
        float ux = vx * inv, uy = vy * inv, uz = vz * inv;

        float xx = ux * ux, yy = uy * uy, zz = uz * uz;
        float Y1 = s3 * ux, Y2 = s3 * uy, Y3 = s3 * uz;
        float Y4 = s15 * ux * uy, Y5 = s15 * uy * uz;
        float Y6 = 0.5f * s5 * (3.f * zz - 1.f);
        float Y7 = s15 * ux * uz;
        float Y8 = 0.5f * s15 * (xx - yy);
        float Y9 = s35_8 * uy * (3.f * xx - yy);
        float Y10 = s105 * ux * uy * uz;
        float Y11 = s21_8 * uy * (5.f * zz - 1.f);
        float Y12 = 0.5f * s7 * uz * (5.f * zz - 3.f);
        float Y13 = s21_8 * ux * (5.f * zz - 1.f);
        float Y14 = 0.5f * s105 * uz * (xx - yy);
        float Y15 = s35_8 * ux * (xx - 3.f * yy);

        float tp = fminf(lng * TBL_SCALE, (float)TBL - 1.001f);
        int it = (int)tp;
        float fr = tp - (float)it;
        const float4 w0 = *(const float4*)(tb + (size_t)it * 512 + (c << 2));
        const float4 w1 = *(const float4*)(tb + (size_t)(it + 1) * 512 + (c << 2));
        float Rw0 = (w0.x + fr * (w1.x - w0.x)) * env;
        float Rw1 = (w0.y + fr * (w1.y - w0.y)) * env;
        float Rw2 = (w0.z + fr * (w1.z - w0.z)) * env;
        float Rw3 = (w0.w + fr * (w1.w - w0.w)) * env;

        const float* vrow = vbase + s * 3 * FF;
        float f = zbase[s * FF + c];
        f = fmaf(vrow[c], ux, f);
        f = fmaf(vrow[FF + c], uy, f);
        f = fmaf(vrow[2 * FF + c], uz, f);

        float t0 = Rw0 * f, t1 = Rw1 * f, t2 = Rw2 * f, t3 = Rw3 * f;
        A[0] += t0;
        A[1]  = fmaf(t1, Y1,  A[1]);
        A[2]  = fmaf(t1, Y2,  A[2]);
        A[3]  = fmaf(t1, Y3,  A[3]);
        A[4]  = fmaf(t2, Y4,  A[4]);
        A[5]  = fmaf(t2, Y5,  A[5]);
        A[6]  = fmaf(t2, Y6,  A[6]);
        A[7]  = fmaf(t2, Y7,  A[7]);
        A[8]  = fmaf(t2, Y8,  A[8]);
        A[9]  = fmaf(t3, Y9,  A[9]);
        A[10] = fmaf(t3, Y10, A[10]);
        A[11] = fmaf(t3, Y11, A[11]);
        A[12] = fmaf(t3, Y12, A[12]);
        A[13] = fmaf(t3, Y13, A[13]);
        A[14] = fmaf(t3, Y14, A[14]);
        A[15] = fmaf(t3, Y15, A[15]);
    }

    if (q > 0) {
#pragma unroll
        for (int k = 0; k < 16; k++) red[q - 1][k * FF + c] = A[k];
    }
    __syncthreads();

    if (q == 0) {
#pragma unroll
        for (int k = 0; k < 16; k++)
            A[k] = (A[k] + red[0][k * FF + c] + red[1][k * FF + c] + red[2][k * FF + c])
                   * (1.0f / 16.0f);

        float n0 = A[0] * A[0];
        float n1 = A[1] * A[1] + A[2] * A[2] + A[3] * A[3];

        const int co = (layer * 4) * FF + c;
        float g0 = 1.f + c1w[co]      * n0 + c2w[co]      * n0 * n0 + c3w[co]      * n0 * n0 * n0;
        float g1 = 1.f + c1w[co + FF] * n1 + c2w[co + FF] * n1 * n1 + c3w[co + FF] * n1 * n1 * n1;

        sA[c]          = A[0] * g0;
        sA[FF + c]     = A[1] * g1;
        sA[2 * FF + c] = A[2] * g1;
        sA[3 * FF + c] = A[3] * g1;
    }
    __syncthreads();

    // ---- node update (all 512 threads; k-range split over q) ----
    float* part = &red[0][0];   // reuse reduction smem: [4][4*FF]
    const float* M0 = Wmix0 + layer * FF * FF;
    const float* M1 = Wmix1 + layer * FF * FF;
    {
        float sc = 0.f, v0 = 0.f, v1 = 0.f, v2 = 0.f;
        const float* m0p = M0 + q * 32 * FF + c;
        const float* m1p = M1 + q * 32 * FF + c;
        const float* a0p = sA + q * 32;
#pragma unroll
        for (int kk = 0; kk < 32; kk++) {
            float m0 = m0p[kk * FF];
            float m1 = m1p[kk * FF];
            sc = fmaf(a0p[kk],          m0, sc);
            v0 = fmaf(a0p[FF + kk],     m1, v0);
            v1 = fmaf(a0p[2 * FF + kk], m1, v1);
            v2 = fmaf(a0p[3 * FF + kk], m1, v2);
        }
        part[q * 4 * FF + c]          = sc;
        part[q * 4 * FF + FF + c]     = v0;
        part[q * 4 * FF + 2 * FF + c] = v1;
        part[q * 4 * FF + 3 * FF + c] = v2;
    }
    __syncthreads();

    float sc = part[c] + part[4*FF + c] + part[8*FF + c] + part[12*FF + c];
    float v0 = part[FF + c] + part[5*FF + c] + part[9*FF + c] + part[13*FF + c];
    float v1 = part[2*FF + c] + part[6*FF + c] + part[10*FF + c] + part[14*FF + c];
    float v2 = part[3*FF + c] + part[7*FF + c] + part[11*FF + c] + part[15*FF + c];
    if (q == 0) sscal[c] = sc;
    __syncthreads();

    if (c < 16) {
        const float* G1 = Wg1 + layer * FF * 16;
        float a = 0.f;
#pragma unroll
        for (int kk = 0; kk < 32; kk++) {
            int k = q * 32 + kk;
            a = fmaf(sscal[k], G1[k * 16 + c], a);
        }
        shp[q][c] = a;
    }
    __syncthreads();
    if (q == 0 && c < 16) {
        float a = shp[0][c] + shp[1][c] + shp[2][c] + shp[3][c];
        sh[c] = a / (1.0f + expf(-a));
    }
    __syncthreads();

    if (q == 0) {
        const float* G2 = Wg2 + layer * 16 * FF;
        float gate = 0.f;
#pragma unroll
        for (int j = 0; j < 16; j++) gate = fmaf(sh[j], G2[j * FF + c], gate);
        float w = gate * Wvout[layer * FF + c];

        float m0 = v0 * w, m1 = v1 * w, m2 = v2 * w;
#pragma unroll
        for (int off = 16; off > 0; off >>= 1) {
            m0 += __shfl_down_sync(0xffffffffu, m0, off);
            m1 += __shfl_down_sync(0xffffffffu, m1, off);
            m2 += __shfl_down_sync(0xffffffffu, m2, off);
        }
        if ((c & 31) == 0) {
            int wp = c >> 5;
            rb[0][wp] = m0; rb[1][wp] = m1; rb[2][wp] = m2;
        }
    }
    __syncthreads();

    if (q == 0) {
        if (c < 3) {
            float pnew = sp[r * 3 + c] + rb[c][0] + rb[c][1] + rb[c][2] + rb[c][3];
            g_posbuf[1 - p][bn * 3 + c] = pnew;
            if (layer == LL - 1)
                out[bn * 3 + c] = pnew - pos_in[bn * 3 + c];
        }
        float* vn = g_vecbuf[1 - p] + bn * 3 * FF;
        vn[c] = v0; vn[FF + c] = v1; vn[2 * FF + c] = v2;
    }

    if (layer + 1 < LL) {
        const float* W = Wnode + (layer + 1) * FF * FF + q * 32 * FF + c;
        float acc = 0.f;
#pragma unroll
        for (int kk = 0; kk < 32; kk++)
            acc = fmaf(sscal[q * 32 + kk], W[kk * FF], acc);
        __syncthreads();
        part[q * FF + c] = acc;
        __syncthreads();
        if (q == 0)
            g_zbuf[1 - p][bn * FF + c] = part[c] + part[FF + c] + part[2*FF + c] + part[3*FF + c];
    }
}

// ---------------------------------------------------------------------------
extern "C" void kernel_launch(void* const* d_in, const int* in_sizes, int n_in,
                              void* d_out, int out_size) {
    const float* positions     = (const float*)d_in[0];
    const int*   node_features = (const int*)d_in[1];
    const float* gf            = (const float*)d_in[2];
    const float* W_embed       = (const float*)d_in[3];
    const float* b_embed       = (const float*)d_in[4];
    const float* Wr1           = (const float*)d_in[5];
    const float* br1           = (const float*)d_in[6];
    const float* Wr2           = (const float*)d_in[7];
    const float* Wnode         = (const float*)d_in[8];
    const float* c1w           = (const float*)d_in[9];
    const float* c2w           = (const float*)d_in[10];
    const float* c3w           = (const float*)d_in[11];
    const float* Wmix0         = (const float*)d_in[12];
    const float* Wmix1         = (const float*)d_in[13];
    const float* Wg1           = (const float*)d_in[14];
    const float* Wg2           = (const float*)d_in[15];
    const float* Wvout         = (const float*)d_in[16];
    float* out = (float*)d_out;

    k_tables<<<dim3(TBL / 8, LL), 128>>>(Wr1, br1, Wr2);
    k_init<<<BB * NN, 128>>>(positions, node_features, gf, W_embed, b_embed, Wnode);
    for (int i = 0; i < LL; i++)
        k_layer<<<dim3(NN, BB), dim3(128, 4)>>>(positions, c1w, c2w, c3w,
                                                Wmix0, Wmix1, Wg1, Wg2, Wvout, Wnode,
                                                out, i);
}

// round 5
// speedup vs baseline: 2.2599x; 2.2599x over previous
#include <cuda_runtime.h>
#include <math.h>

#define BB 4
#define NN 128
#define FF 128
#define SS 5
#define TGLOB 32
#define LL 2
#define TBL 512
#define LMAX 16.0f
#define TBL_SCALE (TBL / LMAX)

// ---------------- persistent scratch (device globals; no allocation) ------
__device__ float g_posbuf[2][BB * NN * 3];
__device__ float4 g_veczbuf[2][BB * NN * FF];     // (v0,v1,v2,z) per node-channel
__device__ float g_A4[BB * NN * 4 * FF];          // gated A for k=0..3
__device__ float g_tbl[LL * TBL * 512];           // radial table [layer][t][c*4+j]

// ---------------- table build: 8 rows per block for Wr2 reuse -------------
__global__ __launch_bounds__(128) void k_tables(const float* __restrict__ Wr1,
                                                const float* __restrict__ br1,
                                                const float* __restrict__ Wr2) {
    const int tb0 = blockIdx.x * 8;
    const int i = blockIdx.y;
    const int c = threadIdx.x;
    __shared__ float h[8][64];
    if (c < 64) {
        float w1 = Wr1[i * 64 + c];
        float b1 = br1[i * 64 + c];
#pragma unroll
        for (int j = 0; j < 8; j++) {
            float lng = (float)(tb0 + j) * (LMAX / (float)TBL);
            float p = lng * w1 + b1;
            h[j][c] = p / (1.0f + expf(-p));
        }
    }
    __syncthreads();
    const float* W = Wr2 + i * 64 * 512 + c;
    float acc[8][4];
#pragma unroll
    for (int j = 0; j < 8; j++)
#pragma unroll
        for (int d = 0; d < 4; d++) acc[j][d] = 0.f;
#pragma unroll 4
    for (int m = 0; m < 64; m++) {
        float w0 = W[m * 512 + 0];
        float w1v = W[m * 512 + 128];
        float w2 = W[m * 512 + 256];
        float w3 = W[m * 512 + 384];
#pragma unroll
        for (int j = 0; j < 8; j++) {
            float hm = h[j][m];
            acc[j][0] = fmaf(hm, w0, acc[j][0]);
            acc[j][1] = fmaf(hm, w1v, acc[j][1]);
            acc[j][2] = fmaf(hm, w2, acc[j][2]);
            acc[j][3] = fmaf(hm, w3, acc[j][3]);
        }
    }
#pragma unroll
    for (int j = 0; j < 8; j++) {
        float* dst = g_tbl + ((size_t)i * TBL + tb0 + j) * 512 + c * 4;
        dst[0] = acc[j][0]; dst[1] = acc[j][1]; dst[2] = acc[j][2]; dst[3] = acc[j][3];
    }
}

// ---------------- init: embed scalars, z(layer0), zero vec, pos -----------
__global__ __launch_bounds__(128) void k_init(const float* __restrict__ positions,
                                              const int* __restrict__ node_features,
                                              const float* __restrict__ gf,
                                              const float* __restrict__ W_embed,
                                              const float* __restrict__ b_embed,
                                              const float* __restrict__ Wnode) {
    int bn = blockIdx.x;
    int b = bn / NN;
    int c = threadIdx.x;
    int nf = node_features[bn];
    float s = W_embed[(nf - 1) * FF + c] + b_embed[c];
#pragma unroll 8
    for (int t = 0; t < TGLOB; t++)
        s = fmaf(gf[b * TGLOB + t], W_embed[(SS + t) * FF + c], s);
    if (c < 3) g_posbuf[0][bn * 3 + c] = positions[bn * 3 + c];

    __shared__ float srow[FF];
    srow[c] = s;
    __syncthreads();
    float acc = 0.f;
#pragma unroll 8
    for (int k = 0; k < FF; k++)
        acc = fmaf(srow[k], Wnode[k * FF + c], acc);
    g_veczbuf[0][bn * FF + c] = make_float4(0.f, 0.f, 0.f, acc);
}

// ---------------- message gather + gate --------------------------------
// blockDim (128,2): c = channel, q = sender half [q*64, q*64+64)
__global__ __launch_bounds__(256, 4) void k_msg(const float* __restrict__ pos_in,
                                                const float* __restrict__ c1w,
                                                const float* __restrict__ c2w,
                                                const float* __restrict__ c3w,
                                                int layer) {
    const int r = blockIdx.x;
    const int b = blockIdx.y;
    const int c = threadIdx.x;
    const int q = threadIdx.y;
    const int tid = q * 128 + c;
    const int p = layer & 1;

    __shared__ float sp[NN * 3];
    __shared__ float sp0[NN * 3];
    __shared__ float4 sData[NN][6];
    __shared__ float red[16 * FF];

    for (int idx = tid; idx < NN * 3; idx += 256) {
        sp[idx]  = g_posbuf[p][b * NN * 3 + idx];
        sp0[idx] = pos_in[b * NN * 3 + idx];
    }
    __syncthreads();

    // ---- phase 1: per-sender geometry (one thread per sender) ----
    if (tid < NN) {
        const int s = tid;
        const float rx = sp[r * 3 + 0], ry = sp[r * 3 + 1], rz = sp[r * 3 + 2];
        float dx0 = sp0[r * 3 + 0] - sp0[s * 3 + 0];
        float dy0 = sp0[r * 3 + 1] - sp0[s * 3 + 1];
        float dz0 = sp0[r * 3 + 2] - sp0[s * 3 + 2];
        float l0 = sqrtf(dx0 * dx0 + dy0 * dy0 + dz0 * dz0 + 1e-12f);
        float env = (l0 < 10.0f) ? 0.5f * (cosf(l0 * 0.3141592653589793f) + 1.0f) : 0.0f;
        if (s == r) env = 0.0f;

        float vx = rx - sp[s * 3 + 0];
        float vy = ry - sp[s * 3 + 1];
        float vz = rz - sp[s * 3 + 2];
        float lng = sqrtf(vx * vx + vy * vy + vz * vz + 1e-12f);
        float inv = 1.0f / lng;
        float ux = vx * inv, uy = vy * inv, uz = vz * inv;

        const float s3 = 1.7320508075688772f, s5 = 2.2360679774997896f,
                    s15 = 3.872983346207417f, s35_8 = 2.091650066335189f,
                    s105 = 10.246950765959598f, s21_8 = 1.6201851746019651f,
                    s7 = 2.6457513110645907f;
        float xx = ux * ux, yy = uy * uy, zz = uz * uz;
        float Y1 = s3 * ux, Y2 = s3 * uy, Y3 = s3 * uz;
        float Y4 = s15 * ux * uy, Y5 = s15 * uy * uz;
        float Y6 = 0.5f * s5 * (3.f * zz - 1.f);
        float Y7 = s15 * ux * uz;
        float Y8 = 0.5f * s15 * (xx - yy);
        float Y9 = s35_8 * uy * (3.f * xx - yy);
        float Y10 = s105 * ux * uy * uz;
        float Y11 = s21_8 * uy * (5.f * zz - 1.f);
        float Y12 = 0.5f * s7 * uz * (5.f * zz - 3.f);
        float Y13 = s21_8 * ux * (5.f * zz - 1.f);
        float Y14 = 0.5f * s105 * uz * (xx - yy);
        float Y15 = s35_8 * ux * (xx - 3.f * yy);

        float tp = fminf(lng * TBL_SCALE, (float)TBL - 1.001f);
        int it = (int)tp;
        float fr = tp - (float)it;
        float a0 = env * (1.0f - fr);
        float a1 = env * fr;

        sData[s][0] = make_float4(ux, uy, uz, a0);
        sData[s][1] = make_float4(a1, (float)it, Y1, Y2);
        sData[s][2] = make_float4(Y3, Y4, Y5, Y6);
        sData[s][3] = make_float4(Y7, Y8, Y9, Y10);
        sData[s][4] = make_float4(Y11, Y12, Y13, Y14);
        sData[s][5] = make_float4(Y15, 0.f, 0.f, 0.f);
    }
    __syncthreads();

    // ---- phase 2: per-channel accumulation ----
    float A[16];
#pragma unroll
    for (int k = 0; k < 16; k++) A[k] = 0.f;

    const float* tb = g_tbl + (size_t)layer * TBL * 512;
    const float4* vecz = g_veczbuf[p] + b * NN * FF;

#pragma unroll 4
    for (int s = q * 64; s < q * 64 + 64; s++) {
        float4 d0 = sData[s][0];
        float4 d1 = sData[s][1];
        float a0 = d0.w, a1 = d1.x;
        int it = (int)d1.y;
        const float4 w0 = *(const float4*)(tb + (size_t)it * 512 + (c << 2));
        const float4 w1 = *(const float4*)(tb + (size_t)it * 512 + 512 + (c << 2));
        float Rw0 = fmaf(a0, w0.x, a1 * w1.x);
        float Rw1 = fmaf(a0, w0.y, a1 * w1.y);
        float Rw2 = fmaf(a0, w0.z, a1 * w1.z);
        float Rw3 = fmaf(a0, w0.w, a1 * w1.w);

        float4 vz = vecz[s * FF + c];
        float f = vz.w;
        f = fmaf(vz.x, d0.x, f);
        f = fmaf(vz.y, d0.y, f);
        f = fmaf(vz.z, d0.z, f);

        float t0 = Rw0 * f, t1 = Rw1 * f, t2 = Rw2 * f, t3 = Rw3 * f;
        float4 d2 = sData[s][2];
        float4 d3 = sData[s][3];
        float4 d4 = sData[s][4];
        float4 d5 = sData[s][5];
        A[0] += t0;
        A[1]  = fmaf(t1, d1.z, A[1]);
        A[2]  = fmaf(t1, d1.w, A[2]);
        A[3]  = fmaf(t1, d2.x, A[3]);
        A[4]  = fmaf(t2, d2.y, A[4]);
        A[5]  = fmaf(t2, d2.z, A[5]);
        A[6]  = fmaf(t2, d2.w, A[6]);
        A[7]  = fmaf(t2, d3.x, A[7]);
        A[8]  = fmaf(t2, d3.y, A[8]);
        A[9]  = fmaf(t3, d3.z, A[9]);
        A[10] = fmaf(t3, d3.w, A[10]);
        A[11] = fmaf(t3, d4.x, A[11]);
        A[12] = fmaf(t3, d4.y, A[12]);
        A[13] = fmaf(t3, d4.z, A[13]);
        A[14] = fmaf(t3, d4.w, A[14]);
        A[15] = fmaf(t3, d5.x, A[15]);
    }

    if (q == 1) {
#pragma unroll
        for (int k = 0; k < 16; k++) red[k * FF + c] = A[k];
    }
    __syncthreads();
    if (q != 0) return;

#pragma unroll
    for (int k = 0; k < 16; k++)
        A[k] = (A[k] + red[k * FF + c]) * (1.0f / 16.0f);

    float n0 = A[0] * A[0];
    float n1 = A[1] * A[1] + A[2] * A[2] + A[3] * A[3];

    const int co = (layer * 4) * FF + c;
    float g0 = 1.f + c1w[co]      * n0 + c2w[co]      * n0 * n0 + c3w[co]      * n0 * n0 * n0;
    float g1 = 1.f + c1w[co + FF] * n1 + c2w[co + FF] * n1 * n1 + c3w[co + FF] * n1 * n1 * n1;

    float* dst = g_A4 + ((size_t)(b * NN + r)) * 4 * FF;
    dst[c]          = A[0] * g0;
    dst[FF + c]     = A[1] * g1;
    dst[2 * FF + c] = A[2] * g1;
    dst[3 * FF + c] = A[3] * g1;
}

// ---------------- node update ----------------------------------------------
// blockDim (128,2): c = output channel, q = k-half [q*64, q*64+64)
__global__ __launch_bounds__(256, 4) void k_node(const float* __restrict__ pos_in,
                                                 const float* __restrict__ Wmix0,
                                                 const float* __restrict__ Wmix1,
                                                 const float* __restrict__ Wg1,
                                                 const float* __restrict__ Wg2,
                                                 const float* __restrict__ Wvout,
                                                 const float* __restrict__ Wnode,
                                                 float* __restrict__ out,
                                                 int layer) {
    const int bn = blockIdx.x;
    const int c = threadIdx.x;
    const int q = threadIdx.y;
    const int tid = q * 128 + c;
    const int p = layer & 1;

    __shared__ float sA[4 * FF];
    __shared__ float part[2][4 * FF];
    __shared__ float sscal[FF];
    __shared__ float shp[2][16];
    __shared__ float sh[16];
    __shared__ float rb[3][4];

    const float* asrc = g_A4 + (size_t)bn * 4 * FF;
    for (int idx = tid; idx < 4 * FF; idx += 256) sA[idx] = asrc[idx];
    __syncthreads();

    const float* M0 = Wmix0 + layer * FF * FF + q * 64 * FF + c;
    const float* M1 = Wmix1 + layer * FF * FF + q * 64 * FF + c;
    {
        float sc = 0.f, v0 = 0.f, v1 = 0.f, v2 = 0.f;
        const float* a0p = sA + q * 64;
#pragma unroll 8
        for (int kk = 0; kk < 64; kk++) {
            float m0 = M0[kk * FF];
            float m1 = M1[kk * FF];
            sc = fmaf(a0p[kk],          m0, sc);
            v0 = fmaf(a0p[FF + kk],     m1, v0);
            v1 = fmaf(a0p[2 * FF + kk], m1, v1);
            v2 = fmaf(a0p[3 * FF + kk], m1, v2);
        }
        part[q][c]          = sc;
        part[q][FF + c]     = v0;
        part[q][2 * FF + c] = v1;
        part[q][3 * FF + c] = v2;
    }
    __syncthreads();

    float sc = part[0][c] + part[1][c];
    float v0 = part[0][FF + c] + part[1][FF + c];
    float v1 = part[0][2 * FF + c] + part[1][2 * FF + c];
    float v2 = part[0][3 * FF + c] + part[1][3 * FF + c];
    if (q == 0) sscal[c] = sc;
    __syncthreads();

    if (c < 16) {
        const float* G1 = Wg1 + layer * FF * 16;
        float a = 0.f;
#pragma unroll 8
        for (int kk = 0; kk < 64; kk++) {
            int k = q * 64 + kk;
            a = fmaf(sscal[k], G1[k * 16 + c], a);
        }
        shp[q][c] = a;
    }
    __syncthreads();
    if (q == 0 && c < 16) {
        float a = shp[0][c] + shp[1][c];
        sh[c] = a / (1.0f + expf(-a));
    }
    __syncthreads();

    if (q == 0) {
        const float* G2 = Wg2 + layer * 16 * FF;
        float gate = 0.f;
#pragma unroll
        for (int j = 0; j < 16; j++) gate = fmaf(sh[j], G2[j * FF + c], gate);
        float w = gate * Wvout[layer * FF + c];

        float m0 = v0 * w, m1 = v1 * w, m2 = v2 * w;
#pragma unroll
        for (int off = 16; off > 0; off >>= 1) {
            m0 += __shfl_down_sync(0xffffffffu, m0, off);
            m1 += __shfl_down_sync(0xffffffffu, m1, off);
            m2 += __shfl_down_sync(0xffffffffu, m2, off);
        }
        if ((c & 31) == 0) {
            int wp = c >> 5;
            rb[0][wp] = m0; rb[1][wp] = m1; rb[2][wp] = m2;
        }
    }

    // z for next layer (needs sscal complete)
    float zpart = 0.f;
    if (layer + 1 < LL) {
        const float* W = Wnode + (layer + 1) * FF * FF + q * 64 * FF + c;
#pragma unroll 8
        for (int kk = 0; kk < 64; kk++)
            zpart = fmaf(sscal[q * 64 + kk], W[kk * FF], zpart);
    }
    __syncthreads();
    part[q][c] = zpart;
    __syncthreads();

    if (q == 0) {
        if (c < 3) {
            float pnew = g_posbuf[p][bn * 3 + c] + rb[c][0] + rb[c][1] + rb[c][2] + rb[c][3];
            g_posbuf[1 - p][bn * 3 + c] = pnew;
            if (layer == LL - 1)
                out[bn * 3 + c] = pnew - pos_in[bn * 3 + c];
        }
        float zn = part[0][c] + part[1][c];
        g_veczbuf[1 - p][bn * FF + c] = make_float4(v0, v1, v2, zn);
    }
}

// ---------------------------------------------------------------------------
extern "C" void kernel_launch(void* const* d_in, const int* in_sizes, int n_in,
                              void* d_out, int out_size) {
    const float* positions     = (const float*)d_in[0];
    const int*   node_features = (const int*)d_in[1];
    const float* gf            = (const float*)d_in[2];
    const float* W_embed       = (const float*)d_in[3];
    const float* b_embed       = (const float*)d_in[4];
    const float* Wr1           = (const float*)d_in[5];
    const float* br1           = (const float*)d_in[6];
    const float* Wr2           = (const float*)d_in[7];
    const float* Wnode         = (const float*)d_in[8];
    const float* c1w           = (const float*)d_in[9];
    const float* c2w           = (const float*)d_in[10];
    const float* c3w           = (const float*)d_in[11];
    const float* Wmix0         = (const float*)d_in[12];
    const float* Wmix1         = (const float*)d_in[13];
    const float* Wg1           = (const float*)d_in[14];
    const float* Wg2           = (const float*)d_in[15];
    const float* Wvout         = (const float*)d_in[16];
    float* out = (float*)d_out;

    k_tables<<<dim3(TBL / 8, LL), 128>>>(Wr1, br1, Wr2);
    k_init<<<BB * NN, 128>>>(positions, node_features, gf, W_embed, b_embed, Wnode);
    for (int i = 0; i < LL; i++) {
        k_msg<<<dim3(NN, BB), dim3(128, 2)>>>(positions, c1w, c2w, c3w, i);
        k_node<<<BB * NN, dim3(128, 2)>>>(positions, Wmix0, Wmix1, Wg1, Wg2, Wvout,
                                          Wnode, out, i);
    }
}

// round 6
// speedup vs baseline: 2.4306x; 1.0756x over previous
#include <cuda_runtime.h>
#include <math.h>

#define BB 4
#define NN 128
#define FF 128
#define SS 5
#define TGLOB 32
#define LL 2
#define TBL 512
#define LMAX 16.0f
#define TBL_SCALE (TBL / LMAX)
#define TBLK (TBL / 8)          /* table blocks per layer = 64 */

// ---------------- persistent scratch (device globals; no allocation) ------
__device__ float g_posbuf[2][BB * NN * 3];
__device__ float4 g_veczbuf[2][BB * NN * FF];     // (v0,v1,v2,z) per node-channel
__device__ float g_A4[BB * NN * 4 * FF];          // gated A for k=0..3
__device__ float g_tbl[LL * TBL * 512];           // radial table [layer][t][c*4+j]

// ---------------- fused prep: radial tables + embed/init ------------------
__global__ __launch_bounds__(128) void k_prep(const float* __restrict__ Wr1,
                                              const float* __restrict__ br1,
                                              const float* __restrict__ Wr2,
                                              const float* __restrict__ positions,
                                              const int* __restrict__ node_features,
                                              const float* __restrict__ gf,
                                              const float* __restrict__ W_embed,
                                              const float* __restrict__ b_embed,
                                              const float* __restrict__ Wnode) {
    const int c = threadIdx.x;
    if (blockIdx.x < TBLK * LL) {
        // ---- table part ----
        const int i = blockIdx.x / TBLK;          // layer
        const int tb0 = (blockIdx.x % TBLK) * 8;  // first of 8 rows
        __shared__ float h[8][64];
        if (c < 64) {
            float w1 = Wr1[i * 64 + c];
            float b1 = br1[i * 64 + c];
#pragma unroll
            for (int j = 0; j < 8; j++) {
                float lng = (float)(tb0 + j) * (LMAX / (float)TBL);
                float p = lng * w1 + b1;
                h[j][c] = p / (1.0f + expf(-p));
            }
        }
        __syncthreads();
        const float* W = Wr2 + i * 64 * 512 + c;
        float acc[8][4];
#pragma unroll
        for (int j = 0; j < 8; j++)
#pragma unroll
            for (int d = 0; d < 4; d++) acc[j][d] = 0.f;
#pragma unroll 4
        for (int m = 0; m < 64; m++) {
            float w0 = W[m * 512 + 0];
            float w1v = W[m * 512 + 128];
            float w2 = W[m * 512 + 256];
            float w3 = W[m * 512 + 384];
#pragma unroll
            for (int j = 0; j < 8; j++) {
                float hm = h[j][m];
                acc[j][0] = fmaf(hm, w0, acc[j][0]);
                acc[j][1] = fmaf(hm, w1v, acc[j][1]);
                acc[j][2] = fmaf(hm, w2, acc[j][2]);
                acc[j][3] = fmaf(hm, w3, acc[j][3]);
            }
        }
#pragma unroll
        for (int j = 0; j < 8; j++) {
            float* dst = g_tbl + ((size_t)i * TBL + tb0 + j) * 512 + c * 4;
            dst[0] = acc[j][0]; dst[1] = acc[j][1]; dst[2] = acc[j][2]; dst[3] = acc[j][3];
        }
    } else {
        // ---- init part ----
        const int bn = blockIdx.x - TBLK * LL;
        const int b = bn / NN;
        int nf = node_features[bn];
        float s = W_embed[(nf - 1) * FF + c] + b_embed[c];
#pragma unroll 8
        for (int t = 0; t < TGLOB; t++)
            s = fmaf(gf[b * TGLOB + t], W_embed[(SS + t) * FF + c], s);
        if (c < 3) g_posbuf[0][bn * 3 + c] = positions[bn * 3 + c];

        __shared__ float srow[FF];
        srow[c] = s;
        __syncthreads();
        float acc = 0.f;
#pragma unroll 8
        for (int k = 0; k < FF; k++)
            acc = fmaf(srow[k], Wnode[k * FF + c], acc);
        g_veczbuf[0][bn * FF + c] = make_float4(0.f, 0.f, 0.f, acc);
    }
}

// ---------------- message gather + gate --------------------------------
// blockDim (128,2): c = channel, q = sender half [q*64, q*64+64)
__global__ __launch_bounds__(256, 4) void k_msg(const float* __restrict__ pos_in,
                                                const float* __restrict__ c1w,
                                                const float* __restrict__ c2w,
                                                const float* __restrict__ c3w,
                                                int layer) {
    const int r = blockIdx.x;
    const int b = blockIdx.y;
    const int c = threadIdx.x;
    const int q = threadIdx.y;
    const int tid = q * 128 + c;
    const int p = layer & 1;

    __shared__ float sp[NN * 3];
    __shared__ float sp0[NN * 3];
    __shared__ float4 sData[NN][6];
    __shared__ float red[16 * FF];

    for (int idx = tid; idx < NN * 3; idx += 256) {
        sp[idx]  = g_posbuf[p][b * NN * 3 + idx];
        sp0[idx] = pos_in[b * NN * 3 + idx];
    }
    __syncthreads();

    if (tid < NN) {
        const int s = tid;
        const float rx = sp[r * 3 + 0], ry = sp[r * 3 + 1], rz = sp[r * 3 + 2];
        float dx0 = sp0[r * 3 + 0] - sp0[s * 3 + 0];
        float dy0 = sp0[r * 3 + 1] - sp0[s * 3 + 1];
        float dz0 = sp0[r * 3 + 2] - sp0[s * 3 + 2];
        float l0 = sqrtf(dx0 * dx0 + dy0 * dy0 + dz0 * dz0 + 1e-12f);
        float env = (l0 < 10.0f) ? 0.5f * (cosf(l0 * 0.3141592653589793f) + 1.0f) : 0.0f;
        if (s == r) env = 0.0f;

        float vx = rx - sp[s * 3 + 0];
        float vy = ry - sp[s * 3 + 1];
        float vz = rz - sp[s * 3 + 2];
        float lng = sqrtf(vx * vx + vy * vy + vz * vz + 1e-12f);
        float inv = 1.0f / lng;
        float ux = vx * inv, uy = vy * inv, uz = vz * inv;

        const float s3 = 1.7320508075688772f, s5 = 2.2360679774997896f,
                    s15 = 3.872983346207417f, s35_8 = 2.091650066335189f,
                    s105 = 10.246950765959598f, s21_8 = 1.6201851746019651f,
                    s7 = 2.6457513110645907f;
        float xx = ux * ux, yy = uy * uy, zz = uz * uz;
        float Y1 = s3 * ux, Y2 = s3 * uy, Y3 = s3 * uz;
        float Y4 = s15 * ux * uy, Y5 = s15 * uy * uz;
        float Y6 = 0.5f * s5 * (3.f * zz - 1.f);
        float Y7 = s15 * ux * uz;
        float Y8 = 0.5f * s15 * (xx - yy);
        float Y9 = s35_8 * uy * (3.f * xx - yy);
        float Y10 = s105 * ux * uy * uz;
        float Y11 = s21_8 * uy * (5.f * zz - 1.f);
        float Y12 = 0.5f * s7 * uz * (5.f * zz - 3.f);
        float Y13 = s21_8 * ux * (5.f * zz - 1.f);
        float Y14 = 0.5f * s105 * uz * (xx - yy);
        float Y15 = s35_8 * ux * (xx - 3.f * yy);

        float tp = fminf(lng * TBL_SCALE, (float)TBL - 1.001f);
        int it = (int)tp;
        float fr = tp - (float)it;
        float a0 = env * (1.0f - fr);
        float a1 = env * fr;

        sData[s][0] = make_float4(ux, uy, uz, a0);
        sData[s][1] = make_float4(a1, (float)it, Y1, Y2);
        sData[s][2] = make_float4(Y3, Y4, Y5, Y6);
        sData[s][3] = make_float4(Y7, Y8, Y9, Y10);
        sData[s][4] = make_float4(Y11, Y12, Y13, Y14);
        sData[s][5] = make_float4(Y15, 0.f, 0.f, 0.f);
    }
    __syncthreads();

    float A[16];
#pragma unroll
    for (int k = 0; k < 16; k++) A[k] = 0.f;

    const float* tb = g_tbl + (size_t)layer * TBL * 512;
    const float4* vecz = g_veczbuf[p] + b * NN * FF;

#pragma unroll 4
    for (int s = q * 64; s < q * 64 + 64; s++) {
        float4 d0 = sData[s][0];
        float4 d1 = sData[s][1];
        float a0 = d0.w, a1 = d1.x;
        int it = (int)d1.y;
        const float4 w0 = *(const float4*)(tb + (size_t)it * 512 + (c << 2));
        const float4 w1 = *(const float4*)(tb + (size_t)it * 512 + 512 + (c << 2));
        float Rw0 = fmaf(a0, w0.x, a1 * w1.x);
        float Rw1 = fmaf(a0, w0.y, a1 * w1.y);
        float Rw2 = fmaf(a0, w0.z, a1 * w1.z);
        float Rw3 = fmaf(a0, w0.w, a1 * w1.w);

        float4 vz = vecz[s * FF + c];
        float f = vz.w;
        f = fmaf(vz.x, d0.x, f);
        f = fmaf(vz.y, d0.y, f);
        f = fmaf(vz.z, d0.z, f);

        float t0 = Rw0 * f, t1 = Rw1 * f, t2 = Rw2 * f, t3 = Rw3 * f;
        float4 d2 = sData[s][2];
        float4 d3 = sData[s][3];
        float4 d4 = sData[s][4];
        float4 d5 = sData[s][5];
        A[0] += t0;
        A[1]  = fmaf(t1, d1.z, A[1]);
        A[2]  = fmaf(t1, d1.w, A[2]);
        A[3]  = fmaf(t1, d2.x, A[3]);
        A[4]  = fmaf(t2, d2.y, A[4]);
        A[5]  = fmaf(t2, d2.z, A[5]);
        A[6]  = fmaf(t2, d2.w, A[6]);
        A[7]  = fmaf(t2, d3.x, A[7]);
        A[8]  = fmaf(t2, d3.y, A[8]);
        A[9]  = fmaf(t3, d3.z, A[9]);
        A[10] = fmaf(t3, d3.w, A[10]);
        A[11] = fmaf(t3, d4.x, A[11]);
        A[12] = fmaf(t3, d4.y, A[12]);
        A[13] = fmaf(t3, d4.z, A[13]);
        A[14] = fmaf(t3, d4.w, A[14]);
        A[15] = fmaf(t3, d5.x, A[15]);
    }

    if (q == 1) {
#pragma unroll
        for (int k = 0; k < 16; k++) red[k * FF + c] = A[k];
    }
    __syncthreads();
    if (q != 0) return;

#pragma unroll
    for (int k = 0; k < 16; k++)
        A[k] = (A[k] + red[k * FF + c]) * (1.0f / 16.0f);

    float n0 = A[0] * A[0];
    float n1 = A[1] * A[1] + A[2] * A[2] + A[3] * A[3];

    const int co = (layer * 4) * FF + c;
    float g0 = 1.f + c1w[co]      * n0 + c2w[co]      * n0 * n0 + c3w[co]      * n0 * n0 * n0;
    float g1 = 1.f + c1w[co + FF] * n1 + c2w[co + FF] * n1 * n1 + c3w[co + FF] * n1 * n1 * n1;

    float* dst = g_A4 + ((size_t)(b * NN + r)) * 4 * FF;
    dst[c]          = A[0] * g0;
    dst[FF + c]     = A[1] * g1;
    dst[2 * FF + c] = A[2] * g1;
    dst[3 * FF + c] = A[3] * g1;
}

// ---------------- node update ----------------------------------------------
// blockDim (32,8): lane owns 4 channels (float4), q = k-slice [q*16, q*16+16)
__global__ __launch_bounds__(256, 4) void k_node(const float* __restrict__ pos_in,
                                                 const float* __restrict__ Wmix0,
                                                 const float* __restrict__ Wmix1,
                                                 const float* __restrict__ Wg1,
                                                 const float* __restrict__ Wg2,
                                                 const float* __restrict__ Wvout,
                                                 const float* __restrict__ Wnode,
                                                 float* __restrict__ out,
                                                 int layer) {
    const int bn = blockIdx.x;
    const int lane = threadIdx.x;
    const int q = threadIdx.y;
    const int tid = q * 32 + lane;
    const int c4 = lane * 4;
    const int p = layer & 1;

    __shared__ float sA[4 * FF];
    __shared__ float part[8][4 * FF];
    __shared__ float sred[4 * FF];
    __shared__ float shp[2][16];
    __shared__ float sh[16];
    __shared__ float rb[3][4];
    __shared__ float zred[FF];

    const float* asrc = g_A4 + (size_t)bn * 4 * FF;
    for (int idx = tid; idx < 4 * FF; idx += 256) sA[idx] = asrc[idx];
    __syncthreads();

    // ---- Wmix0/Wmix1 GEMV: float4 weight loads, 8-way k split ----
    {
        const float* M0 = Wmix0 + layer * FF * FF + c4;
        const float* M1 = Wmix1 + layer * FF * FF + c4;
        float4 sc = make_float4(0.f, 0.f, 0.f, 0.f);
        float4 v0 = sc, v1 = sc, v2 = sc;
#pragma unroll
        for (int kk = 0; kk < 16; kk++) {
            int k = q * 16 + kk;
            float4 m0 = *(const float4*)(M0 + k * FF);
            float4 m1 = *(const float4*)(M1 + k * FF);
            float aS = sA[k], a0 = sA[FF + k], a1 = sA[2 * FF + k], a2 = sA[3 * FF + k];
            sc.x = fmaf(aS, m0.x, sc.x); sc.y = fmaf(aS, m0.y, sc.y);
            sc.z = fmaf(aS, m0.z, sc.z); sc.w = fmaf(aS, m0.w, sc.w);
            v0.x = fmaf(a0, m1.x, v0.x); v0.y = fmaf(a0, m1.y, v0.y);
            v0.z = fmaf(a0, m1.z, v0.z); v0.w = fmaf(a0, m1.w, v0.w);
            v1.x = fmaf(a1, m1.x, v1.x); v1.y = fmaf(a1, m1.y, v1.y);
            v1.z = fmaf(a1, m1.z, v1.z); v1.w = fmaf(a1, m1.w, v1.w);
            v2.x = fmaf(a2, m1.x, v2.x); v2.y = fmaf(a2, m1.y, v2.y);
            v2.z = fmaf(a2, m1.z, v2.z); v2.w = fmaf(a2, m1.w, v2.w);
        }
        *(float4*)&part[q][0 * FF + c4] = sc;
        *(float4*)&part[q][1 * FF + c4] = v0;
        *(float4*)&part[q][2 * FF + c4] = v1;
        *(float4*)&part[q][3 * FF + c4] = v2;
    }
    __syncthreads();

    // ---- 8-way reduction (512 values, 256 threads) ----
    for (int idx = tid; idx < 4 * FF; idx += 256) {
        float s = 0.f;
#pragma unroll
        for (int qq = 0; qq < 8; qq++) s += part[qq][idx];
        sred[idx] = s;
    }
    __syncthreads();

    // ---- Wg1 (128->16): 32 threads, 2-way k split ----
    if (tid < 32) {
        int cc = tid & 15, hf = tid >> 4;
        const float* G1 = Wg1 + layer * FF * 16 + cc;
        float a = 0.f;
#pragma unroll 8
        for (int kk = 0; kk < 64; kk++) {
            int k = hf * 64 + kk;
            a = fmaf(sred[k], G1[k * 16], a);
        }
        shp[hf][cc] = a;
    }
    __syncthreads();
    if (tid < 16) {
        float a = shp[0][tid] + shp[1][tid];
        sh[tid] = a / (1.0f + expf(-a));
    }
    __syncthreads();

    // ---- gate + position reduce: 128 threads (c = tid) ----
    if (tid < 128) {
        const int c = tid;
        const float* G2 = Wg2 + layer * 16 * FF;
        float gate = 0.f;
#pragma unroll
        for (int j = 0; j < 16; j++) gate = fmaf(sh[j], G2[j * FF + c], gate);
        float w = gate * Wvout[layer * FF + c];
        float m0 = sred[FF + c] * w;
        float m1 = sred[2 * FF + c] * w;
        float m2 = sred[3 * FF + c] * w;
#pragma unroll
        for (int off = 16; off > 0; off >>= 1) {
            m0 += __shfl_down_sync(0xffffffffu, m0, off);
            m1 += __shfl_down_sync(0xffffffffu, m1, off);
            m2 += __shfl_down_sync(0xffffffffu, m2, off);
        }
        if ((c & 31) == 0) {
            int wp = c >> 5;
            rb[0][wp] = m0; rb[1][wp] = m1; rb[2][wp] = m2;
        }
    }
    __syncthreads();
    if (tid < 3) {
        float pnew = g_posbuf[p][bn * 3 + tid] + rb[tid][0] + rb[tid][1] + rb[tid][2] + rb[tid][3];
        g_posbuf[1 - p][bn * 3 + tid] = pnew;
        if (layer == LL - 1)
            out[bn * 3 + tid] = pnew - pos_in[bn * 3 + tid];
    }

    // ---- next-layer z GEMV: same float4 layout ----
    if (layer + 1 < LL) {
        const float* W = Wnode + (layer + 1) * FF * FF + c4;
        float4 acc = make_float4(0.f, 0.f, 0.f, 0.f);
#pragma unroll
        for (int kk = 0; kk < 16; kk++) {
            int k = q * 16 + kk;
            float4 w4 = *(const float4*)(W + k * FF);
            float s = sred[k];
            acc.x = fmaf(s, w4.x, acc.x); acc.y = fmaf(s, w4.y, acc.y);
            acc.z = fmaf(s, w4.z, acc.z); acc.w = fmaf(s, w4.w, acc.w);
        }
        __syncthreads();
        *(float4*)&part[q][c4] = acc;
        __syncthreads();
        if (tid < FF) {
            float s = 0.f;
#pragma unroll
            for (int qq = 0; qq < 8; qq++) s += part[qq][tid];
            zred[tid] = s;
        }
        __syncthreads();
    }

    if (tid < 128) {
        const int c = tid;
        float zn = (layer + 1 < LL) ? zred[c] : 0.f;
        g_veczbuf[1 - p][bn * FF + c] =
            make_float4(sred[FF + c], sred[2 * FF + c], sred[3 * FF + c], zn);
    }
}

// ---------------------------------------------------------------------------
extern "C" void kernel_launch(void* const* d_in, const int* in_sizes, int n_in,
                              void* d_out, int out_size) {
    const float* positions     = (const float*)d_in[0];
    const int*   node_features = (const int*)d_in[1];
    const float* gf            = (const float*)d_in[2];
    const float* W_embed       = (const float*)d_in[3];
    const float* b_embed       = (const float*)d_in[4];
    const float* Wr1           = (const float*)d_in[5];
    const float* br1           = (const float*)d_in[6];
    const float* Wr2           = (const float*)d_in[7];
    const float* Wnode         = (const float*)d_in[8];
    const float* c1w           = (const float*)d_in[9];
    const float* c2w           = (const float*)d_in[10];
    const float* c3w           = (const float*)d_in[11];
    const float* Wmix0         = (const float*)d_in[12];
    const float* Wmix1         = (const float*)d_in[13];
    const float* Wg1           = (const float*)d_in[14];
    const float* Wg2           = (const float*)d_in[15];
    const float* Wvout         = (const float*)d_in[16];
    float* out = (float*)d_out;

    k_prep<<<TBLK * LL + BB * NN, 128>>>(Wr1, br1, Wr2, positions, node_features,
                                         gf, W_embed, b_embed, Wnode);
    for (int i = 0; i < LL; i++) {
        k_msg<<<dim3(NN, BB), dim3(128, 2)>>>(positions, c1w, c2w, c3w, i);
        k_node<<<BB * NN, dim3(32, 8)>>>(positions, Wmix0, Wmix1, Wg1, Wg2, Wvout,
                                         Wnode, out, i);
    }
}

// round 7
// speedup vs baseline: 2.7910x; 1.1483x over previous
#include <cuda_runtime.h>
#include <cuda_fp16.h>
#include <math.h>

#define BB 4
#define NN 128
#define FF 128
#define SS 5
#define TGLOB 32
#define LL 2
#define TBL 512
#define LMAX 16.0f
#define TBL_SCALE (TBL / LMAX)
#define TBLK (TBL / 8)          /* table blocks per layer = 64 */

// ---------------- persistent scratch (device globals; no allocation) ------
__device__ float g_posbuf[2][BB * NN * 3];
__device__ float4 g_veczbuf[2][BB * NN * FF];     // (v0,v1,v2,z) per node-channel
__device__ float g_A4[BB * NN * 4 * FF];          // gated A for k=0..3
__device__ __half2 g_tblh[LL * TBL * 512];        // (w_t, w_{t+1}) pairs, [layer][t][c*4+j]

// ---------------- fused prep: radial tables (half2 pairs) + embed/init ----
__global__ __launch_bounds__(128) void k_prep(const float* __restrict__ Wr1,
                                              const float* __restrict__ br1,
                                              const float* __restrict__ Wr2,
                                              const float* __restrict__ positions,
                                              const int* __restrict__ node_features,
                                              const float* __restrict__ gf,
                                              const float* __restrict__ W_embed,
                                              const float* __restrict__ b_embed,
                                              const float* __restrict__ Wnode) {
    const int c = threadIdx.x;
    if (blockIdx.x < TBLK * LL) {
        // ---- table part: compute 9 rows (overlap 1), store 8 half2-pairs ----
        const int i = blockIdx.x / TBLK;          // layer
        const int tb0 = (blockIdx.x % TBLK) * 8;  // first of 8 pair rows
        __shared__ float h[9][64];
        if (c < 64) {
            float w1 = Wr1[i * 64 + c];
            float b1 = br1[i * 64 + c];
#pragma unroll
            for (int j = 0; j < 9; j++) {
                float lng = (float)(tb0 + j) * (LMAX / (float)TBL);
                float p = lng * w1 + b1;
                h[j][c] = p / (1.0f + expf(-p));
            }
        }
        __syncthreads();
        const float* W = Wr2 + i * 64 * 512 + c;
        float acc[9][4];
#pragma unroll
        for (int j = 0; j < 9; j++)
#pragma unroll
            for (int d = 0; d < 4; d++) acc[j][d] = 0.f;
#pragma unroll 4
        for (int m = 0; m < 64; m++) {
            float w0 = W[m * 512 + 0];
            float w1v = W[m * 512 + 128];
            float w2 = W[m * 512 + 256];
            float w3 = W[m * 512 + 384];
#pragma unroll
            for (int j = 0; j < 9; j++) {
                float hm = h[j][m];
                acc[j][0] = fmaf(hm, w0, acc[j][0]);
                acc[j][1] = fmaf(hm, w1v, acc[j][1]);
                acc[j][2] = fmaf(hm, w2, acc[j][2]);
                acc[j][3] = fmaf(hm, w3, acc[j][3]);
            }
        }
#pragma unroll
        for (int j = 0; j < 8; j++) {
            __half2* dst = g_tblh + ((size_t)i * TBL + tb0 + j) * 512 + c * 4;
#pragma unroll
            for (int d = 0; d < 4; d++)
                dst[d] = __float22half2_rn(make_float2(acc[j][d], acc[j + 1][d]));
        }
    } else {
        // ---- init part ----
        const int bn = blockIdx.x - TBLK * LL;
        const int b = bn / NN;
        int nf = node_features[bn];
        float s = W_embed[(nf - 1) * FF + c] + b_embed[c];
#pragma unroll 8
        for (int t = 0; t < TGLOB; t++)
            s = fmaf(gf[b * TGLOB + t], W_embed[(SS + t) * FF + c], s);
        if (c < 3) g_posbuf[0][bn * 3 + c] = positions[bn * 3 + c];

        __shared__ float srow[FF];
        srow[c] = s;
        __syncthreads();
        float acc = 0.f;
#pragma unroll 8
        for (int k = 0; k < FF; k++)
            acc = fmaf(srow[k], Wnode[k * FF + c], acc);
        g_veczbuf[0][bn * FF + c] = make_float4(0.f, 0.f, 0.f, acc);
    }
}

// ---------------- message gather + gate --------------------------------
// blockDim (128,2): c = channel, q = sender half [q*64, q*64+64)
__global__ __launch_bounds__(256, 4) void k_msg(const float* __restrict__ pos_in,
                                                const float* __restrict__ c1w,
                                                const float* __restrict__ c2w,
                                                const float* __restrict__ c3w,
                                                int layer) {
    const int r = blockIdx.x;
    const int b = blockIdx.y;
    const int c = threadIdx.x;
    const int q = threadIdx.y;
    const int tid = q * 128 + c;
    const int p = layer & 1;

    __shared__ float sp[NN * 3];
    __shared__ float sp0[NN * 3];
    __shared__ float4 sData[NN][5];
    __shared__ float red[16 * FF];

    for (int idx = tid; idx < NN * 3; idx += 256) {
        sp[idx]  = g_posbuf[p][b * NN * 3 + idx];
        sp0[idx] = pos_in[b * NN * 3 + idx];
    }
    __syncthreads();

    if (tid < NN) {
        const int s = tid;
        const float rx = sp[r * 3 + 0], ry = sp[r * 3 + 1], rz = sp[r * 3 + 2];
        float dx0 = sp0[r * 3 + 0] - sp0[s * 3 + 0];
        float dy0 = sp0[r * 3 + 1] - sp0[s * 3 + 1];
        float dz0 = sp0[r * 3 + 2] - sp0[s * 3 + 2];
        float l0 = sqrtf(dx0 * dx0 + dy0 * dy0 + dz0 * dz0 + 1e-12f);
        float env = (l0 < 10.0f) ? 0.5f * (cosf(l0 * 0.3141592653589793f) + 1.0f) : 0.0f;
        if (s == r) env = 0.0f;

        float vx = rx - sp[s * 3 + 0];
        float vy = ry - sp[s * 3 + 1];
        float vz = rz - sp[s * 3 + 2];
        float lng = sqrtf(vx * vx + vy * vy + vz * vz + 1e-12f);
        float inv = 1.0f / lng;
        float ux = vx * inv, uy = vy * inv, uz = vz * inv;

        const float s5 = 2.2360679774997896f,
                    s15 = 3.872983346207417f, s35_8 = 2.091650066335189f,
                    s105 = 10.246950765959598f, s21_8 = 1.6201851746019651f,
                    s7 = 2.6457513110645907f;
        float xx = ux * ux, yy = uy * uy, zz = uz * uz;
        float Y4 = s15 * ux * uy, Y5 = s15 * uy * uz;
        float Y6 = 0.5f * s5 * (3.f * zz - 1.f);
        float Y7 = s15 * ux * uz;
        float Y8 = 0.5f * s15 * (xx - yy);
        float Y9 = s35_8 * uy * (3.f * xx - yy);
        float Y10 = s105 * ux * uy * uz;
        float Y11 = s21_8 * uy * (5.f * zz - 1.f);
        float Y12 = 0.5f * s7 * uz * (5.f * zz - 3.f);
        float Y13 = s21_8 * ux * (5.f * zz - 1.f);
        float Y14 = 0.5f * s105 * uz * (xx - yy);
        float Y15 = s35_8 * ux * (xx - 3.f * yy);

        float tp = fminf(lng * TBL_SCALE, (float)TBL - 1.001f);
        int it = (int)tp;
        float fr = tp - (float)it;
        float a0 = env * (1.0f - fr);
        float a1 = env * fr;

        sData[s][0] = make_float4(ux, uy, uz, a0);
        sData[s][1] = make_float4(a1, __int_as_float(it), Y4, Y5);
        sData[s][2] = make_float4(Y6, Y7, Y8, Y9);
        sData[s][3] = make_float4(Y10, Y11, Y12, Y13);
        sData[s][4] = make_float4(Y14, Y15, 0.f, 0.f);
    }
    __syncthreads();

    float A[16];
#pragma unroll
    for (int k = 0; k < 16; k++) A[k] = 0.f;

    const __half2* tb = g_tblh + (size_t)layer * TBL * 512;
    const float4* vecz = g_veczbuf[p] + b * NN * FF;
    const float s3 = 1.7320508075688772f;

#pragma unroll 4
    for (int s = q * 64; s < q * 64 + 64; s++) {
        float4 d0 = sData[s][0];
        float4 d1 = sData[s][1];
        float a0 = d0.w, a1 = d1.x;
        int it = __float_as_int(d1.y);

        // one 16B load: 4 half2 pairs = both lerp endpoints for all 4 ells
        uint4 w = *(const uint4*)(tb + (size_t)it * 512 + (c << 2));
        float2 f0 = __half22float2(*reinterpret_cast<const __half2*>(&w.x));
        float2 f1 = __half22float2(*reinterpret_cast<const __half2*>(&w.y));
        float2 f2 = __half22float2(*reinterpret_cast<const __half2*>(&w.z));
        float2 f3 = __half22float2(*reinterpret_cast<const __half2*>(&w.w));
        float Rw0 = fmaf(a0, f0.x, a1 * f0.y);
        float Rw1 = fmaf(a0, f1.x, a1 * f1.y);
        float Rw2 = fmaf(a0, f2.x, a1 * f2.y);
        float Rw3 = fmaf(a0, f3.x, a1 * f3.y);

        float4 vz = vecz[s * FF + c];
        float f = vz.w;
        f = fmaf(vz.x, d0.x, f);
        f = fmaf(vz.y, d0.y, f);
        f = fmaf(vz.z, d0.z, f);

        float t0 = Rw0 * f, t1 = Rw1 * f, t2 = Rw2 * f, t3 = Rw3 * f;
        float t1s = t1 * s3;
        float4 d2 = sData[s][2];
        float4 d3 = sData[s][3];
        float4 d4 = sData[s][4];
        A[0] += t0;
        A[1]  = fmaf(t1s, d0.x, A[1]);
        A[2]  = fmaf(t1s, d0.y, A[2]);
        A[3]  = fmaf(t1s, d0.z, A[3]);
        A[4]  = fmaf(t2, d1.z, A[4]);
        A[5]  = fmaf(t2, d1.w, A[5]);
        A[6]  = fmaf(t2, d2.x, A[6]);
        A[7]  = fmaf(t2, d2.y, A[7]);
        A[8]  = fmaf(t2, d2.z, A[8]);
        A[9]  = fmaf(t3, d2.w, A[9]);
        A[10] = fmaf(t3, d3.x, A[10]);
        A[11] = fmaf(t3, d3.y, A[11]);
        A[12] = fmaf(t3, d3.z, A[12]);
        A[13] = fmaf(t3, d3.w, A[13]);
        A[14] = fmaf(t3, d4.x, A[14]);
        A[15] = fmaf(t3, d4.y, A[15]);
    }

    if (q == 1) {
#pragma unroll
        for (int k = 0; k < 16; k++) red[k * FF + c] = A[k];
    }
    __syncthreads();
    if (q != 0) return;

#pragma unroll
    for (int k = 0; k < 16; k++)
        A[k] = (A[k] + red[k * FF + c]) * (1.0f / 16.0f);

    float n0 = A[0] * A[0];
    float n1 = A[1] * A[1] + A[2] * A[2] + A[3] * A[3];

    const int co = (layer * 4) * FF + c;
    float g0 = 1.f + c1w[co]      * n0 + c2w[co]      * n0 * n0 + c3w[co]      * n0 * n0 * n0;
    float g1 = 1.f + c1w[co + FF] * n1 + c2w[co + FF] * n1 * n1 + c3w[co + FF] * n1 * n1 * n1;

    float* dst = g_A4 + ((size_t)(b * NN + r)) * 4 * FF;
    dst[c]          = A[0] * g0;
    dst[FF + c]     = A[1] * g1;
    dst[2 * FF + c] = A[2] * g1;
    dst[3 * FF + c] = A[3] * g1;
}

// ---------------- node update ----------------------------------------------
// blockDim (32,8): lane owns 4 channels (float4), q = k-slice [q*16, q*16+16)
__global__ __launch_bounds__(256, 4) void k_node(const float* __restrict__ pos_in,
                                                 const float* __restrict__ Wmix0,
                                                 const float* __restrict__ Wmix1,
                                                 const float* __restrict__ Wg1,
                                                 const float* __restrict__ Wg2,
                                                 const float* __restrict__ Wvout,
                                                 const float* __restrict__ Wnode,
                                                 float* __restrict__ out,
                                                 int layer) {
    const int bn = blockIdx.x;
    const int lane = threadIdx.x;
    const int q = threadIdx.y;
    const int tid = q * 32 + lane;
    const int c4 = lane * 4;
    const int p = layer & 1;

    __shared__ float sA[4 * FF];
    __shared__ float part[8][4 * FF];
    __shared__ float sred[4 * FF];
    __shared__ float shp[2][16];
    __shared__ float sh[16];
    __shared__ float rb[3][4];
    __shared__ float zred[FF];

    const float* asrc = g_A4 + (size_t)bn * 4 * FF;
    for (int idx = tid; idx < 4 * FF; idx += 256) sA[idx] = asrc[idx];
    __syncthreads();

    {
        const float* M0 = Wmix0 + layer * FF * FF + c4;
        const float* M1 = Wmix1 + layer * FF * FF + c4;
        float4 sc = make_float4(0.f, 0.f, 0.f, 0.f);
        float4 v0 = sc, v1 = sc, v2 = sc;
#pragma unroll
        for (int kk = 0; kk < 16; kk++) {
            int k = q * 16 + kk;
            float4 m0 = *(const float4*)(M0 + k * FF);
            float4 m1 = *(const float4*)(M1 + k * FF);
            float aS = sA[k], a0 = sA[FF + k], a1 = sA[2 * FF + k], a2 = sA[3 * FF + k];
            sc.x = fmaf(aS, m0.x, sc.x); sc.y = fmaf(aS, m0.y, sc.y);
            sc.z = fmaf(aS, m0.z, sc.z); sc.w = fmaf(aS, m0.w, sc.w);
            v0.x = fmaf(a0, m1.x, v0.x); v0.y = fmaf(a0, m1.y, v0.y);
            v0.z = fmaf(a0, m1.z, v0.z); v0.w = fmaf(a0, m1.w, v0.w);
            v1.x = fmaf(a1, m1.x, v1.x); v1.y = fmaf(a1, m1.y, v1.y);
            v1.z = fmaf(a1, m1.z, v1.z); v1.w = fmaf(a1, m1.w, v1.w);
            v2.x = fmaf(a2, m1.x, v2.x); v2.y = fmaf(a2, m1.y, v2.y);
            v2.z = fmaf(a2, m1.z, v2.z); v2.w = fmaf(a2, m1.w, v2.w);
        }
        *(float4*)&part[q][0 * FF + c4] = sc;
        *(float4*)&part[q][1 * FF + c4] = v0;
        *(float4*)&part[q][2 * FF + c4] = v1;
        *(float4*)&part[q][3 * FF + c4] = v2;
    }
    __syncthreads();

    for (int idx = tid; idx < 4 * FF; idx += 256) {
        float s = 0.f;
#pragma unroll
        for (int qq = 0; qq < 8; qq++) s += part[qq][idx];
        sred[idx] = s;
    }
    __syncthreads();

    if (tid < 32) {
        int cc = tid & 15, hf = tid >> 4;
        const float* G1 = Wg1 + layer * FF * 16 + cc;
        float a = 0.f;
#pragma unroll 8
        for (int kk = 0; kk < 64; kk++) {
            int k = hf * 64 + kk;
            a = fmaf(sred[k], G1[k * 16], a);
        }
        shp[hf][cc] = a;
    }
    __syncthreads();
    if (tid < 16) {
        float a = shp[0][tid] + shp[1][tid];
        sh[tid] = a / (1.0f + expf(-a));
    }
    __syncthreads();

    if (tid < 128) {
        const int c = tid;
        const float* G2 = Wg2 + layer * 16 * FF;
        float gate = 0.f;
#pragma unroll
        for (int j = 0; j < 16; j++) gate = fmaf(sh[j], G2[j * FF + c], gate);
        float w = gate * Wvout[layer * FF + c];
        float m0 = sred[FF + c] * w;
        float m1 = sred[2 * FF + c] * w;
        float m2 = sred[3 * FF + c] * w;
#pragma unroll
        for (int off = 16; off > 0; off >>= 1) {
            m0 += __shfl_down_sync(0xffffffffu, m0, off);
            m1 += __shfl_down_sync(0xffffffffu, m1, off);
            m2 += __shfl_down_sync(0xffffffffu, m2, off);
        }
        if ((c & 31) == 0) {
            int wp = c >> 5;
            rb[0][wp] = m0; rb[1][wp] = m1; rb[2][wp] = m2;
        }
    }
    __syncthreads();
    if (tid < 3) {
        float pnew = g_posbuf[p][bn * 3 + tid] + rb[tid][0] + rb[tid][1] + rb[tid][2] + rb[tid][3];
        g_posbuf[1 - p][bn * 3 + tid] = pnew;
        if (layer == LL - 1)
            out[bn * 3 + tid] = pnew - pos_in[bn * 3 + tid];
    }

    if (layer + 1 < LL) {
        const float* W = Wnode + (layer + 1) * FF * FF + c4;
        float4 acc = make_float4(0.f, 0.f, 0.f, 0.f);
#pragma unroll
        for (int kk = 0; kk < 16; kk++) {
            int k = q * 16 + kk;
            float4 w4 = *(const float4*)(W + k * FF);
            float s = sred[k];
            acc.x = fmaf(s, w4.x, acc.x); acc.y = fmaf(s, w4.y, acc.y);
            acc.z = fmaf(s, w4.z, acc.z); acc.w = fmaf(s, w4.w, acc.w);
        }
        __syncthreads();
        *(float4*)&part[q][c4] = acc;
        __syncthreads();
        if (tid < FF) {
            float s = 0.f;
#pragma unroll
            for (int qq = 0; qq < 8; qq++) s += part[qq][tid];
            zred[tid] = s;
        }
        __syncthreads();
    }

    if (tid < 128) {
        const int c = tid;
        float zn = (layer + 1 < LL) ? zred[c] : 0.f;
        g_veczbuf[1 - p][bn * FF + c] =
            make_float4(sred[FF + c], sred[2 * FF + c], sred[3 * FF + c], zn);
    }
}

// ---------------------------------------------------------------------------
extern "C" void kernel_launch(void* const* d_in, const int* in_sizes, int n_in,
                              void* d_out, int out_size) {
    const float* positions     = (const float*)d_in[0];
    const int*   node_features = (const int*)d_in[1];
    const float* gf            = (const float*)d_in[2];
    const float* W_embed       = (const float*)d_in[3];
    const float* b_embed       = (const float*)d_in[4];
    const float* Wr1           = (const float*)d_in[5];
    const float* br1           = (const float*)d_in[6];
    const float* Wr2           = (const float*)d_in[7];
    const float* Wnode         = (const float*)d_in[8];
    const float* c1w           = (const float*)d_in[9];
    const float* c2w           = (const float*)d_in[10];
    const float* c3w           = (const float*)d_in[11];
    const float* Wmix0         = (const float*)d_in[12];
    const float* Wmix1         = (const float*)d_in[13];
    const float* Wg1           = (const float*)d_in[14];
    const float* Wg2           = (const float*)d_in[15];
    const float* Wvout         = (const float*)d_in[16];
    float* out = (float*)d_out;

    k_prep<<<TBLK * LL + BB * NN, 128>>>(Wr1, br1, Wr2, positions, node_features,
                                         gf, W_embed, b_embed, Wnode);
    for (int i = 0; i < LL; i++) {
        k_msg<<<dim3(NN, BB), dim3(128, 2)>>>(positions, c1w, c2w, c3w, i);
        k_node<<<BB * NN, dim3(32, 8)>>>(positions, Wmix0, Wmix1, Wg1, Wg2, Wvout,
                                         Wnode, out, i);
    }
}